// round 15
// baseline (speedup 1.0000x reference)
#include <cuda_runtime.h>
#include <cstdint>

#define BS_TOK     524288            // B*S = 512*1024
#define VOCAB      100000
#define N_PRIV     8
#define MAX_CANDS  4000
#define CTX_RATE   0.15f
#define PRI_RATE   1.0f

// Output (float32, flattened, bools as 0/1):
//   obf_word | inp_word | obf_char(32*BS) | inp_pos | obf_mask | pri_mask | cpy_mask

__global__ __launch_bounds__(128, 16) void alltag_fused_kernel(
    const int*   __restrict__ inp_word,
    const int*   __restrict__ inp_pos,
    const int*   __restrict__ inp_mask,
    const float* __restrict__ ctx_rand,
    const float* __restrict__ pri_rand,
    const float* __restrict__ cand_u,
    const int4*  __restrict__ lut4,       // [VOCAB][8] int4
    const int*   __restrict__ tgt_table,  // [N_POS][MAX_CANDS]
    const int*   __restrict__ counts,     // [N_POS]
    float*       __restrict__ out,
    long long    out_elems)
{
    const int warpid = threadIdx.x >> 5;
    const int lane   = threadIdx.x & 31;

    // ------- 2 tokens per thread; warp owns 64 consecutive tokens -------------
    const int warp_tok0 = (blockIdx.x * 4 + warpid) * 64;

    const long long BS = BS_TOK;
    const bool has_char = (34 * BS <= out_elems);
    const long long tail0 = has_char ? 34 * BS : 2 * BS;

    // ---- front-batched loads (MLP) ----
    const int t0 = warp_tok0 + lane;
    const int t1 = warp_tok0 + 32 + lane;
    const int   w0 = inp_word[t0],  w1 = inp_word[t1];
    const int   p0 = inp_pos[t0],   p1 = inp_pos[t1];
    const float cr0 = ctx_rand[t0], cr1 = ctx_rand[t1];
    const float pr0 = pri_rand[t0], pr1 = pri_rand[t1];
    const float cu0 = cand_u[t0],   cu1 = cand_u[t1];
    const int   im0 = inp_mask[t0], im1 = inp_mask[t1];

    const bool pri0 = (p0 < N_PRIV),           pri1 = (p1 < N_PRIV);
    const bool obf0 = pri0 ? (pr0 < PRI_RATE) : (cr0 < CTX_RATE);
    const bool obf1 = pri1 ? (pr1 < PRI_RATE) : (cr1 < CTX_RATE);

    const int cnt0 = counts[p0], cnt1 = counts[p1];
    int i0 = (int)(cu0 * (float)cnt0);           // f32 RN mul + trunc == XLA
    int i1 = (int)(cu1 * (float)cnt1);
    i0 = min(i0, cnt0 - 1);                      // semantic clamp only
    i1 = min(i1, cnt1 - 1);
    const int cdt0 = tgt_table[p0 * MAX_CANDS + i0];
    const int cdt1 = tgt_table[p1 * MAX_CANDS + i1];

    const int ow0 = obf0 ? cdt0 : w0;
    const int ow1 = obf1 ? cdt1 : w1;

    // ---- guarded scalar stores (streaming) ----
    if (1 * BS <= out_elems) { __stcs(out + t0, (float)ow0); __stcs(out + t1, (float)ow1); }
    if (2 * BS <= out_elems) { __stcs(out + BS_TOK + t0, (float)w0);
                               __stcs(out + BS_TOK + t1, (float)w1); }
    if (tail0 + 1 * BS <= out_elems) { __stcs(out + tail0 + t0, (float)p0);
                                       __stcs(out + tail0 + t1, (float)p1); }
    if (tail0 + 2 * BS <= out_elems) { __stcs(out + tail0 + BS_TOK + t0, obf0 ? 1.f : 0.f);
                                       __stcs(out + tail0 + BS_TOK + t1, obf1 ? 1.f : 0.f); }
    if (tail0 + 3 * BS <= out_elems) { __stcs(out + tail0 + 2*BS_TOK + t0, pri0 ? 1.f : 0.f);
                                       __stcs(out + tail0 + 2*BS_TOK + t1, pri1 ? 1.f : 0.f); }
    if (tail0 + 4 * BS <= out_elems) {
        __stcs(out + tail0 + 3*BS_TOK + t0, (im0 != 0 && w0 == ow0) ? 1.f : 0.f);
        __stcs(out + tail0 + 3*BS_TOK + t1, (im1 != 0 && w1 == ow1) ? 1.f : 0.f);
    }

    // ---- warp-cooperative char gather (champion structure) -------------------
    // Per iteration the warp moves 4 tokens x 128B: sub = lane>>3 picks the
    // token in the group of 4, j = lane&7 picks the 16B chunk within the row.
    if (has_char) {
        float4* __restrict__ out_char4 = (float4*)(out + 2 * BS_TOK);  // [BS][8]
        const int sub = lane >> 3;
        const int j   = lane & 7;
        #pragma unroll
        for (int q = 0; q < 2; ++q) {
            const int qbase = warp_tok0 + q * 32;
            const int owq   = q ? ow1 : ow0;
            #pragma unroll
            for (int k = 0; k < 8; ++k) {
                const int t  = k * 4 + sub;
                const int ww = __shfl_sync(0xffffffffu, owq, t);
                const int4 c = __ldcg(&lut4[(size_t)ww * 8 + j]);
                float4 f;
                f.x = (float)c.x; f.y = (float)c.y;
                f.z = (float)c.z; f.w = (float)c.w;
                __stcs(&out_char4[(size_t)(qbase + t) * 8 + j], f);
            }
        }
    }
}

extern "C" void kernel_launch(void* const* d_in, const int* in_sizes, int n_in,
                              void* d_out, int out_size)
{
    // Positional identification: six per-token buffers in signature order
    // (word, pos, mask, ctx, pri, cand); others picked by size.
    const void* tok[6]; int ntok = 0;
    const void* lut = nullptr; const void* tgt = nullptr;
    const void* c40 = nullptr;

    for (int i = 0; i < n_in; ++i) {
        const long long sz = in_sizes[i];
        if (sz == BS_TOK || sz == (long long)BS_TOK * 4) {
            if (ntok < 6) tok[ntok++] = d_in[i];
        } else if (sz == 3200000 || sz == 12800000) lut = d_in[i];
        else if (sz == 160000 || sz == 640000)      tgt = d_in[i];
        else if ((sz == 40 || sz == 160) && !c40)   c40 = d_in[i];   // first = counts
    }
    if (ntok < 6 && n_in >= 10) {
        tok[0] = d_in[0]; tok[1] = d_in[2]; tok[2] = d_in[3];
        tok[3] = d_in[4]; tok[4] = d_in[5]; tok[5] = d_in[6];
        ntok = 6;
        if (!lut) lut = d_in[7];
        if (!tgt) tgt = d_in[8];
        if (!c40) c40 = d_in[9];
    }
    while (ntok < 6) { tok[ntok] = tok[ntok ? ntok - 1 : 0]; ++ntok; }
    if (!lut) lut = d_in[0];
    if (!tgt) tgt = d_in[0];
    if (!c40) c40 = tgt;

    // 2 tokens/thread, 128-thread blocks: 2048 blocks, all resident in one
    // wave (16 blocks/SM capacity), finer tail balancing than 256-thread blocks.
    alltag_fused_kernel<<<BS_TOK / 256, 128>>>(
        (const int*)tok[0], (const int*)tok[1], (const int*)tok[2],
        (const float*)tok[3], (const float*)tok[4], (const float*)tok[5],
        (const int4*)lut, (const int*)tgt, (const int*)c40,
        (float*)d_out, (long long)out_size);
}

// round 17
// speedup vs baseline: 1.5550x; 1.5550x over previous
#include <cuda_runtime.h>
#include <cstdint>

#define BS_TOK     524288            // B*S = 512*1024
#define VOCAB      100000
#define N_PRIV     8
#define MAX_CANDS  4000
#define CTX_RATE   0.15f
#define PRI_RATE   1.0f

// Output (float32, flattened, bools as 0/1):
//   obf_word | inp_word | obf_char(32*BS) | inp_pos | obf_mask | pri_mask | cpy_mask

__global__ __launch_bounds__(256, 8) void alltag_fused_kernel(
    const int*   __restrict__ inp_word,
    const int*   __restrict__ inp_pos,
    const int*   __restrict__ inp_mask,
    const float* __restrict__ ctx_rand,
    const float* __restrict__ pri_rand,
    const float* __restrict__ cand_u,
    const int4*  __restrict__ lut4,       // [VOCAB][8] int4
    const int*   __restrict__ tgt_table,  // [N_POS][MAX_CANDS]
    const int*   __restrict__ counts,     // [N_POS]
    float*       __restrict__ out,
    long long    out_elems)
{
    const int warpid = threadIdx.x >> 5;
    const int lane   = threadIdx.x & 31;

    // ------- 2 tokens per thread; warp owns 64 consecutive tokens -------------
    const int warp_tok0 = (blockIdx.x * 8 + warpid) * 64;

    const long long BS = BS_TOK;
    const bool has_char = (34 * BS <= out_elems);
    const long long tail0 = has_char ? 34 * BS : 2 * BS;

    // ---- front-batched loads (MLP) ----
    const int t0 = warp_tok0 + lane;
    const int t1 = warp_tok0 + 32 + lane;
    const int   w0 = inp_word[t0],  w1 = inp_word[t1];
    const int   p0 = inp_pos[t0],   p1 = inp_pos[t1];
    const float cr0 = ctx_rand[t0], cr1 = ctx_rand[t1];
    const float pr0 = pri_rand[t0], pr1 = pri_rand[t1];
    const float cu0 = cand_u[t0],   cu1 = cand_u[t1];
    const int   im0 = inp_mask[t0], im1 = inp_mask[t1];

    const bool pri0 = (p0 < N_PRIV),           pri1 = (p1 < N_PRIV);
    const bool obf0 = pri0 ? (pr0 < PRI_RATE) : (cr0 < CTX_RATE);
    const bool obf1 = pri1 ? (pr1 < PRI_RATE) : (cr1 < CTX_RATE);

    const int cnt0 = counts[p0], cnt1 = counts[p1];
    int i0 = (int)(cu0 * (float)cnt0);           // f32 RN mul + trunc == XLA
    int i1 = (int)(cu1 * (float)cnt1);
    i0 = min(i0, cnt0 - 1);                      // semantic clamp only
    i1 = min(i1, cnt1 - 1);
    const int cdt0 = tgt_table[p0 * MAX_CANDS + i0];
    const int cdt1 = tgt_table[p1 * MAX_CANDS + i1];

    const int ow0 = obf0 ? cdt0 : w0;
    const int ow1 = obf1 ? cdt1 : w1;

    // ---- guarded scalar stores (streaming) ----
    if (1 * BS <= out_elems) { __stcs(out + t0, (float)ow0); __stcs(out + t1, (float)ow1); }
    if (2 * BS <= out_elems) { __stcs(out + BS_TOK + t0, (float)w0);
                               __stcs(out + BS_TOK + t1, (float)w1); }
    if (tail0 + 1 * BS <= out_elems) { __stcs(out + tail0 + t0, (float)p0);
                                       __stcs(out + tail0 + t1, (float)p1); }
    if (tail0 + 2 * BS <= out_elems) { __stcs(out + tail0 + BS_TOK + t0, obf0 ? 1.f : 0.f);
                                       __stcs(out + tail0 + BS_TOK + t1, obf1 ? 1.f : 0.f); }
    if (tail0 + 3 * BS <= out_elems) { __stcs(out + tail0 + 2*BS_TOK + t0, pri0 ? 1.f : 0.f);
                                       __stcs(out + tail0 + 2*BS_TOK + t1, pri1 ? 1.f : 0.f); }
    if (tail0 + 4 * BS <= out_elems) {
        __stcs(out + tail0 + 3*BS_TOK + t0, (im0 != 0 && w0 == ow0) ? 1.f : 0.f);
        __stcs(out + tail0 + 3*BS_TOK + t1, (im1 != 0 && w1 == ow1) ? 1.f : 0.f);
    }

    // ---- warp-cooperative char gather (champion structure, unchanged) --------
    // Per iteration the warp moves 4 tokens x 128B: sub = lane>>3 picks the
    // token in the group of 4, j = lane&7 picks the 16B chunk within the row.
    if (has_char) {
        float4* __restrict__ out_char4 = (float4*)(out + 2 * BS_TOK);  // [BS][8]
        const int sub = lane >> 3;
        const int j   = lane & 7;
        #pragma unroll
        for (int q = 0; q < 2; ++q) {
            const int qbase = warp_tok0 + q * 32;
            const int owq   = q ? ow1 : ow0;
            #pragma unroll
            for (int k = 0; k < 8; ++k) {
                const int t  = k * 4 + sub;
                const int ww = __shfl_sync(0xffffffffu, owq, t);
                const int4 c = __ldcg(&lut4[(size_t)ww * 8 + j]);
                float4 f;
                f.x = (float)c.x; f.y = (float)c.y;
                f.z = (float)c.z; f.w = (float)c.w;
                __stcs(&out_char4[(size_t)(qbase + t) * 8 + j], f);
            }
        }
    }
}

extern "C" void kernel_launch(void* const* d_in, const int* in_sizes, int n_in,
                              void* d_out, int out_size)
{
    // Positional identification: six per-token buffers in signature order
    // (word, pos, mask, ctx, pri, cand); others picked by size.
    const void* tok[6]; int ntok = 0;
    const void* lut = nullptr; const void* tgt = nullptr;
    const void* c40 = nullptr;

    for (int i = 0; i < n_in; ++i) {
        const long long sz = in_sizes[i];
        if (sz == BS_TOK || sz == (long long)BS_TOK * 4) {
            if (ntok < 6) tok[ntok++] = d_in[i];
        } else if (sz == 3200000 || sz == 12800000) lut = d_in[i];
        else if (sz == 160000 || sz == 640000)      tgt = d_in[i];
        else if ((sz == 40 || sz == 160) && !c40)   c40 = d_in[i];   // first = counts
    }
    if (ntok < 6 && n_in >= 10) {
        tok[0] = d_in[0]; tok[1] = d_in[2]; tok[2] = d_in[3];
        tok[3] = d_in[4]; tok[4] = d_in[5]; tok[5] = d_in[6];
        ntok = 6;
        if (!lut) lut = d_in[7];
        if (!tgt) tgt = d_in[8];
        if (!c40) c40 = d_in[9];
    }
    while (ntok < 6) { tok[ntok] = tok[ntok ? ntok - 1 : 0]; ++ntok; }
    if (!lut) lut = d_in[0];
    if (!tgt) tgt = d_in[0];
    if (!c40) c40 = tgt;

    // R14 champion config: 2 tokens/thread, 1024 blocks of 256 — single wave.
    alltag_fused_kernel<<<BS_TOK / 512, 256>>>(
        (const int*)tok[0], (const int*)tok[1], (const int*)tok[2],
        (const float*)tok[3], (const float*)tok[4], (const float*)tok[5],
        (const int4*)lut, (const int*)tgt, (const int*)c40,
        (float*)d_out, (long long)out_size);
}